// round 14
// baseline (speedup 1.0000x reference)
#include <cuda_runtime.h>
#include <cuda_bf16.h>
#include <cstdint>
#include <math.h>

#define NN     16384
#define EE     524288
#define F_IN   128
#define H1     256
#define H2     256
#define D1     64

// ---------------- scratch (device globals; no allocations) ----------------
// Self-restoring graph state: g_deg / g_gf / g_newadj / g_done / g_done2 reset each call.
__device__ __nv_bfloat16 g_Yb[NN * F_IN];  // dinv[r]*features, bf16
__device__ __nv_bfloat16 g_Zb[NN * F_IN];  // aggregated features, bf16
__device__ __nv_bfloat16 g_h1b[NN * H1];   // relu(Z@W1+b1), bf16
__device__ __nv_bfloat16 g_Xb[NN * H1];    // dinv*(h1@W2), bf16
__device__ __nv_bfloat16 g_h2b[NN * H2];   // layer-2 output, bf16
__device__ float g_dinv[NN];
__device__ int   g_deg[NN];
__device__ int   g_rowptr[NN + 1];
__device__ int   g_slot[EE];
__device__ int   g_col[EE];
__device__ float g_fc1wT[H2 * D1];
__device__ float g_assign[NN * 2];
__device__ float g_gf[2 * H2];
__device__ float g_newadj[4];
__device__ unsigned int g_done;
__device__ unsigned int g_done2;

// ---------------- bf16 SIMD helpers ----------------
__device__ __forceinline__ unsigned int h2add(unsigned int a, unsigned int b) {
    unsigned int r;
    asm("add.rn.bf16x2 %0, %1, %2;" : "=r"(r) : "r"(a), "r"(b));
    return r;
}
__device__ __forceinline__ uint4 h2add4(uint4 a, uint4 b) {
    uint4 r;
    r.x = h2add(a.x, b.x); r.y = h2add(a.y, b.y);
    r.z = h2add(a.z, b.z); r.w = h2add(a.w, b.w);
    return r;
}
__device__ __forceinline__ void acc8(float* acc, uint4 v) {
    float2 a = __bfloat1622float2(*(__nv_bfloat162*)&v.x);
    float2 b = __bfloat1622float2(*(__nv_bfloat162*)&v.y);
    float2 c = __bfloat1622float2(*(__nv_bfloat162*)&v.z);
    float2 e = __bfloat1622float2(*(__nv_bfloat162*)&v.w);
    acc[0] += a.x; acc[1] += a.y; acc[2] += b.x; acc[3] += b.y;
    acc[4] += c.x; acc[5] += c.y; acc[6] += e.x; acc[7] += e.y;
}
__device__ __forceinline__ uint4 pack8(const float* f) {
    __nv_bfloat162 p0 = __floats2bfloat162_rn(f[0], f[1]);
    __nv_bfloat162 p1 = __floats2bfloat162_rn(f[2], f[3]);
    __nv_bfloat162 p2 = __floats2bfloat162_rn(f[4], f[5]);
    __nv_bfloat162 p3 = __floats2bfloat162_rn(f[6], f[7]);
    uint4 o;
    o.x = *(unsigned int*)&p0; o.y = *(unsigned int*)&p1;
    o.z = *(unsigned int*)&p2; o.w = *(unsigned int*)&p3;
    return o;
}

// ---------------- degree histogram + fc1 transpose + last-block scan/dinv ----------------
__global__ __launch_bounds__(1024) void k_deg(const int* __restrict__ dst,
                                              const float* __restrict__ w) {
    __shared__ int wsum[32];
    __shared__ int is_last;
    int i = blockIdx.x * blockDim.x + threadIdx.x;
    g_slot[i] = atomicAdd(&g_deg[dst[i]], 1);
    if (i < D1 * H2) {                           // transpose fc1_w [64,256] -> [256,64]
        int o = i >> 8, k = i & 255;
        g_fc1wT[k * D1 + o] = w[i];
    }
    __threadfence();
    __syncthreads();
    if (threadIdx.x == 0)
        is_last = (atomicAdd(&g_done2, 1) == gridDim.x - 1);
    __syncthreads();
    if (!is_last) return;

    // ---- exclusive scan of in-degrees + dinv (1024 threads x 16) ----
    int t = threadIdx.x;
    int base = t * 16;
    int local[16];
    int s = 0;
    #pragma unroll
    for (int j = 0; j < 16; j++) {
        int dg = __ldcg(&g_deg[base + j]);
        g_dinv[base + j] = rsqrtf((float)(dg + 1));
        local[j] = s;
        s += dg;
    }
    int lane = t & 31, wid = t >> 5;
    int v = s;
    #pragma unroll
    for (int d = 1; d < 32; d <<= 1) {
        int u = __shfl_up_sync(0xffffffffu, v, d);
        if (lane >= d) v += u;
    }
    if (lane == 31) wsum[wid] = v;
    __syncthreads();
    if (wid == 0) {
        int ww = wsum[lane];
        #pragma unroll
        for (int d = 1; d < 32; d <<= 1) {
            int u = __shfl_up_sync(0xffffffffu, ww, d);
            if (lane >= d) ww += u;
        }
        wsum[lane] = ww;
    }
    __syncthreads();
    int off = (v - s) + (wid ? wsum[wid - 1] : 0);
    #pragma unroll
    for (int j = 0; j < 16; j++) g_rowptr[base + j] = off + local[j];
    if (t == 1023) g_rowptr[NN] = off + s;
    if (t == 0) g_done2 = 0;                     // self-restore
}

// ---------------- atomic-free scatter + bf16(dinv*X) convert ----------------
__global__ void k_scatter(const int* __restrict__ src, const int* __restrict__ dst,
                          const float* __restrict__ X) {
    int i = blockIdx.x * blockDim.x + threadIdx.x;
    {
        int d = dst[i];
        g_col[g_rowptr[d] + g_slot[i]] = src[i];
    }
    {
        int node = i >> 5;
        float sc = g_dinv[node];
        float4 v = ((const float4*)X)[i];
        __nv_bfloat162 lo = __floats2bfloat162_rn(v.x * sc, v.y * sc);
        __nv_bfloat162 hi = __floats2bfloat162_rn(v.z * sc, v.w * sc);
        uint2 u; u.x = *(unsigned int*)&lo; u.y = *(unsigned int*)&hi;
        ((uint2*)g_Yb)[i] = u;
    }
}

// ---------------- layer-1 aggregation: 2 warps/node, uint4 gathers, 2 neighbors/warp-step ----------------
// Zb[d] = bf16( dinv[d] * (Yb[d] + sum Yb[s]) ),  Yb pre-scaled by dinv[src]
__global__ __launch_bounds__(256) void k_agg1() {
    __shared__ float part[4][16][8];
    int t = threadIdx.x;
    int w = t >> 5, lane = t & 31;
    int n = w >> 1, half = w & 1;
    int halfw = lane >> 4, l16 = lane & 15;
    int d = blockIdx.x * 4 + n;
    const uint4* Y4 = (const uint4*)g_Yb;   // 16 uint4 per 256B row

    float acc[8] = {};
    int s0 = g_rowptr[d], s1 = g_rowptr[d + 1];
    int len = s1 - s0;
    int j    = s0 + ((len * half) >> 1);
    int jend = s0 + ((len * (half + 1)) >> 1);
    for (; j + 16 <= jend; j += 16) {        // 16 neighbors: 8 per lane-half
        uint4 v[8];
        #pragma unroll
        for (int q = 0; q < 8; q++) {
            int idx = g_col[j + 2 * q + halfw];
            v[q] = Y4[idx * 16 + l16];
        }
        uint4 a0 = h2add4(v[0], v[1]);
        uint4 a1 = h2add4(v[2], v[3]);
        uint4 a2 = h2add4(v[4], v[5]);
        uint4 a3 = h2add4(v[6], v[7]);
        uint4 b0 = h2add4(a0, a1);
        uint4 b1 = h2add4(a2, a3);
        acc8(acc, h2add4(b0, b1));
    }
    for (; j + 2 <= jend; j += 2) {          // 2 neighbors: 1 per lane-half
        int idx = g_col[j + halfw];
        acc8(acc, Y4[idx * 16 + l16]);
    }
    if (j < jend && halfw == 0) {            // odd remainder: lower half only
        int idx = g_col[j];
        acc8(acc, Y4[idx * 16 + l16]);
    }
    // combine lane-halves within warp
    #pragma unroll
    for (int f = 0; f < 8; f++)
        acc[f] += __shfl_down_sync(0xffffffffu, acc[f], 16);
    // combine warp halves
    if (half == 1 && lane < 16) {
        #pragma unroll
        for (int f = 0; f < 8; f++) part[n][lane][f] = acc[f];
    }
    __syncthreads();
    if (half == 0 && lane < 16) {
        float sf[8];
        {   uint4 sv = Y4[d * 16 + lane];    // self term (already dinv[d]-scaled)
            float2 a = __bfloat1622float2(*(__nv_bfloat162*)&sv.x);
            float2 b = __bfloat1622float2(*(__nv_bfloat162*)&sv.y);
            float2 c = __bfloat1622float2(*(__nv_bfloat162*)&sv.z);
            float2 e = __bfloat1622float2(*(__nv_bfloat162*)&sv.w);
            sf[0] = a.x; sf[1] = a.y; sf[2] = b.x; sf[3] = b.y;
            sf[4] = c.x; sf[5] = c.y; sf[6] = e.x; sf[7] = e.y;
        }
        float scd = g_dinv[d];
        float o[8];
        #pragma unroll
        for (int f = 0; f < 8; f++)
            o[f] = (acc[f] + part[n][lane][f] + sf[f]) * scd;
        ((uint4*)g_Zb)[d * 16 + lane] = pack8(o);
    }
}

// ---------------- tf32 helpers ----------------
__device__ __forceinline__ unsigned int f2tf32(float x) {
    unsigned int r;
    asm("cvt.rna.tf32.f32 %0, %1;" : "=r"(r) : "f"(x));
    return r;
}
__device__ __forceinline__ void mma_tf32(float* d, const unsigned int* a, const unsigned int* b) {
    asm volatile(
        "mma.sync.aligned.m16n8k8.row.col.f32.tf32.tf32.f32 "
        "{%0,%1,%2,%3},{%4,%5,%6,%7},{%8,%9},{%0,%1,%2,%3};\n"
        : "+f"(d[0]), "+f"(d[1]), "+f"(d[2]), "+f"(d[3])
        : "r"(a[0]), "r"(a[1]), "r"(a[2]), "r"(a[3]), "r"(b[0]), "r"(b[1]));
}

// ---------------- tf32 GEMM, bf16 A, fp32 B; bf16 out ----------------
// mode 0: Cb = bf16(relu(AB + bias))   mode 1: Cb = bf16(dinv[row] * AB)
#define GBK 32
__global__ __launch_bounds__(256) void k_gemm_tc(const __nv_bfloat16* __restrict__ A,
                                                 const float* __restrict__ B,
                                                 __nv_bfloat16* __restrict__ Cb,
                                                 const float* __restrict__ bias,
                                                 int K, int mode) {
    __shared__ unsigned int As[GBK][136];
    __shared__ unsigned int Bs[GBK][136];
    int t = threadIdx.x;
    int row0 = blockIdx.y * 128, col0 = blockIdx.x * 128;
    int wid = t >> 5, lane = t & 31;
    int wr = wid >> 2, wc = wid & 3;
    int g = lane >> 2, tig = lane & 3;
    float acc[4][4][4] = {};

    int arr = t >> 3, akq = (t & 7) * 4;
    int bkr = t >> 5, bnq = (t & 31) * 4;

    uint2 ra[4];
    float4 rb[4];
    #pragma unroll
    for (int j = 0; j < 4; j++)
        ra[j] = *(const uint2*)&A[(size_t)(row0 + arr + j * 32) * K + akq];
    #pragma unroll
    for (int j = 0; j < 4; j++)
        rb[j] = *(const float4*)&B[(size_t)(bkr + j * 8) * 256 + col0 + bnq];

    for (int k0 = 0; k0 < K; k0 += GBK) {
        #pragma unroll
        for (int j = 0; j < 4; j++) {
            int r = arr + j * 32;
            float2 lo = __bfloat1622float2(*(__nv_bfloat162*)&ra[j].x);
            float2 hi = __bfloat1622float2(*(__nv_bfloat162*)&ra[j].y);
            As[akq + 0][r] = f2tf32(lo.x); As[akq + 1][r] = f2tf32(lo.y);
            As[akq + 2][r] = f2tf32(hi.x); As[akq + 3][r] = f2tf32(hi.y);
        }
        #pragma unroll
        for (int j = 0; j < 4; j++) {
            int kr = bkr + j * 8;
            Bs[kr][bnq + 0] = f2tf32(rb[j].x); Bs[kr][bnq + 1] = f2tf32(rb[j].y);
            Bs[kr][bnq + 2] = f2tf32(rb[j].z); Bs[kr][bnq + 3] = f2tf32(rb[j].w);
        }
        __syncthreads();

        bool more = (k0 + GBK) < K;
        if (more) {
            #pragma unroll
            for (int j = 0; j < 4; j++)
                ra[j] = *(const uint2*)&A[(size_t)(row0 + arr + j * 32) * K + k0 + GBK + akq];
            #pragma unroll
            for (int j = 0; j < 4; j++)
                rb[j] = *(const float4*)&B[(size_t)(k0 + GBK + bkr + j * 8) * 256 + col0 + bnq];
        }

        #pragma unroll
        for (int kk = 0; kk < GBK; kk += 8) {
            unsigned int af[4][4], bf[4][2];
            #pragma unroll
            for (int mi = 0; mi < 4; mi++) {
                int r = wr * 64 + mi * 16 + g;
                af[mi][0] = As[kk + tig][r];
                af[mi][1] = As[kk + tig][r + 8];
                af[mi][2] = As[kk + tig + 4][r];
                af[mi][3] = As[kk + tig + 4][r + 8];
            }
            #pragma unroll
            for (int ni = 0; ni < 4; ni++) {
                int c = wc * 32 + ni * 8 + g;
                bf[ni][0] = Bs[kk + tig][c];
                bf[ni][1] = Bs[kk + tig + 4][c];
            }
            #pragma unroll
            for (int mi = 0; mi < 4; mi++)
                #pragma unroll
                for (int ni = 0; ni < 4; ni++)
                    mma_tf32(acc[mi][ni], af[mi], bf[ni]);
        }
        __syncthreads();
    }

    #pragma unroll
    for (int mi = 0; mi < 4; mi++) {
        #pragma unroll
        for (int half = 0; half < 2; half++) {
            int r = row0 + wr * 64 + mi * 16 + g + half * 8;
            float sc = (mode == 1) ? g_dinv[r] : 1.0f;
            #pragma unroll
            for (int ni = 0; ni < 4; ni++) {
                int c = col0 + wc * 32 + ni * 8 + tig * 2;
                float v0 = acc[mi][ni][half * 2 + 0];
                float v1 = acc[mi][ni][half * 2 + 1];
                if (mode == 0) {
                    v0 = fmaxf(v0 + bias[c], 0.0f);
                    v1 = fmaxf(v1 + bias[c + 1], 0.0f);
                } else {
                    v0 *= sc; v1 *= sc;
                }
                __nv_bfloat162 bv = __floats2bfloat162_rn(v0, v1);
                *(__nv_bfloat162*)&Cb[(size_t)r * 256 + c] = bv;
            }
        }
    }
}

// ---------------- layer-2 aggregation: 2 warps/node, uint4 gathers (full row/warp) ----------------
__global__ __launch_bounds__(256) void k_agg2(const float* __restrict__ bias) {
    __shared__ float part[4][32][8];
    int t = threadIdx.x;
    int w = t >> 5, lane = t & 31;
    int n = w >> 1, half = w & 1;
    int d = blockIdx.x * 4 + n;
    const uint4* X4 = (const uint4*)g_Xb;   // 32 uint4 per 512B row

    float acc[8] = {};
    int s0 = g_rowptr[d], s1 = g_rowptr[d + 1];
    int len = s1 - s0;
    int j    = s0 + ((len * half) >> 1);
    int jend = s0 + ((len * (half + 1)) >> 1);
    for (; j + 8 <= jend; j += 8) {
        uint4 v[8];
        int idx[8];
        #pragma unroll
        for (int q = 0; q < 8; q++) idx[q] = g_col[j + q];
        #pragma unroll
        for (int q = 0; q < 8; q++) v[q] = X4[idx[q] * 32 + lane];
        uint4 a0 = h2add4(v[0], v[1]);
        uint4 a1 = h2add4(v[2], v[3]);
        uint4 a2 = h2add4(v[4], v[5]);
        uint4 a3 = h2add4(v[6], v[7]);
        uint4 b0 = h2add4(a0, a1);
        uint4 b1 = h2add4(a2, a3);
        acc8(acc, h2add4(b0, b1));
    }
    for (; j < jend; j++)
        acc8(acc, X4[g_col[j] * 32 + lane]);

    if (half == 1) {
        #pragma unroll
        for (int f = 0; f < 8; f++) part[n][lane][f] = acc[f];
    }
    __syncthreads();
    if (half == 0) {
        float sf[8];
        {   uint4 sv = X4[d * 32 + lane];   // self term
            float2 a = __bfloat1622float2(*(__nv_bfloat162*)&sv.x);
            float2 b = __bfloat1622float2(*(__nv_bfloat162*)&sv.y);
            float2 c = __bfloat1622float2(*(__nv_bfloat162*)&sv.z);
            float2 e = __bfloat1622float2(*(__nv_bfloat162*)&sv.w);
            sf[0] = a.x; sf[1] = a.y; sf[2] = b.x; sf[3] = b.y;
            sf[4] = c.x; sf[5] = c.y; sf[6] = e.x; sf[7] = e.y;
        }
        float sc = g_dinv[d];
        float4 bv0 = ((const float4*)bias)[lane * 2];
        float4 bv1 = ((const float4*)bias)[lane * 2 + 1];
        float bb[8] = {bv0.x, bv0.y, bv0.z, bv0.w, bv1.x, bv1.y, bv1.z, bv1.w};
        float o[8];
        #pragma unroll
        for (int f = 0; f < 8; f++)
            o[f] = (acc[f] + part[n][lane][f] + sf[f]) * sc + bb[f];
        ((uint4*)g_h2b)[d * 32 + lane] = pack8(o);
    }
}

// ---------------- fused fc1 (tf32 MMA) + fc2 + softmax + assign + gf partials ----------------
__global__ __launch_bounds__(256) void k_fc1fc2(const float* __restrict__ fc1b,
                                                const float* __restrict__ fc2w,
                                                const float* __restrict__ fc2b) {
    __shared__ char buf[36864];
    unsigned int (*As)[136] = (unsigned int(*)[136])buf;
    unsigned int (*Bs)[72]  = (unsigned int(*)[72])(buf + 17408);
    float (*a1s)[65]  = (float(*)[65])buf;
    float (*ps)[2]    = (float(*)[2])(buf + 33280);
    float *w2s        = (float*)(buf + 34304);

    int t = threadIdx.x;
    int row0 = blockIdx.x * 128;
    int wid = t >> 5, lane = t & 31;
    int wr = wid >> 1, wc = wid & 1;
    int g = lane >> 2, tig = lane & 3;
    float acc[2][4][4] = {};

    int arr = t >> 3, akq = (t & 7) * 4;
    int bkr = t >> 3, bcq = (t & 7) * 8;

    const __nv_bfloat16* A = g_h2b;
    uint2 ra[4];
    float4 rb0, rb1;
    #pragma unroll
    for (int j = 0; j < 4; j++)
        ra[j] = *(const uint2*)&A[(size_t)(row0 + arr + j * 32) * 256 + akq];
    rb0 = *(const float4*)&g_fc1wT[(size_t)bkr * 64 + bcq];
    rb1 = *(const float4*)&g_fc1wT[(size_t)bkr * 64 + bcq + 4];

    for (int k0 = 0; k0 < 256; k0 += GBK) {
        #pragma unroll
        for (int j = 0; j < 4; j++) {
            int r = arr + j * 32;
            float2 lo = __bfloat1622float2(*(__nv_bfloat162*)&ra[j].x);
            float2 hi = __bfloat1622float2(*(__nv_bfloat162*)&ra[j].y);
            As[akq + 0][r] = f2tf32(lo.x); As[akq + 1][r] = f2tf32(lo.y);
            As[akq + 2][r] = f2tf32(hi.x); As[akq + 3][r] = f2tf32(hi.y);
        }
        Bs[bkr][bcq + 0] = f2tf32(rb0.x); Bs[bkr][bcq + 1] = f2tf32(rb0.y);
        Bs[bkr][bcq + 2] = f2tf32(rb0.z); Bs[bkr][bcq + 3] = f2tf32(rb0.w);
        Bs[bkr][bcq + 4] = f2tf32(rb1.x); Bs[bkr][bcq + 5] = f2tf32(rb1.y);
        Bs[bkr][bcq + 6] = f2tf32(rb1.z); Bs[bkr][bcq + 7] = f2tf32(rb1.w);
        __syncthreads();

        bool more = (k0 + GBK) < 256;
        if (more) {
            #pragma unroll
            for (int j = 0; j < 4; j++)
                ra[j] = *(const uint2*)&A[(size_t)(row0 + arr + j * 32) * 256 + k0 + GBK + akq];
            rb0 = *(const float4*)&g_fc1wT[(size_t)(k0 + GBK + bkr) * 64 + bcq];
            rb1 = *(const float4*)&g_fc1wT[(size_t)(k0 + GBK + bkr) * 64 + bcq + 4];
        }

        #pragma unroll
        for (int kk = 0; kk < GBK; kk += 8) {
            unsigned int af[2][4], bf[4][2];
            #pragma unroll
            for (int mi = 0; mi < 2; mi++) {
                int r = wr * 32 + mi * 16 + g;
                af[mi][0] = As[kk + tig][r];
                af[mi][1] = As[kk + tig][r + 8];
                af[mi][2] = As[kk + tig + 4][r];
                af[mi][3] = As[kk + tig + 4][r + 8];
            }
            #pragma unroll
            for (int ni = 0; ni < 4; ni++) {
                int c = wc * 32 + ni * 8 + g;
                bf[ni][0] = Bs[kk + tig][c];
                bf[ni][1] = Bs[kk + tig + 4][c];
            }
            #pragma unroll
            for (int mi = 0; mi < 2; mi++)
                #pragma unroll
                for (int ni = 0; ni < 4; ni++)
                    mma_tf32(acc[mi][ni], af[mi], bf[ni]);
        }
        __syncthreads();
    }
    #pragma unroll
    for (int mi = 0; mi < 2; mi++) {
        #pragma unroll
        for (int half = 0; half < 2; half++) {
            int rr = wr * 32 + mi * 16 + g + half * 8;
            #pragma unroll
            for (int ni = 0; ni < 4; ni++) {
                int c = wc * 32 + ni * 8 + tig * 2;
                a1s[rr][c]     = tanhf(acc[mi][ni][half * 2 + 0] + fc1b[c]);
                a1s[rr][c + 1] = tanhf(acc[mi][ni][half * 2 + 1] + fc1b[c + 1]);
            }
        }
    }
    if (t < 128) w2s[t] = fc2w[t];
    __syncthreads();

    {
        int n = t >> 1, c = t & 1;
        float l = fc2b[c];
        #pragma unroll
        for (int k = 0; k < 64; k++) l += w2s[c * 64 + k] * a1s[n][k];
        ps[n][c] = l;
    }
    __syncthreads();
    if (t < 128) {
        float l0 = ps[t][0], l1 = ps[t][1];
        float m = fmaxf(l0, l1);
        float e0 = expf(l0 - m), e1 = expf(l1 - m);
        float inv = 1.0f / (e0 + e1);
        float p0 = e0 * inv, p1 = e1 * inv;
        ps[t][0] = p0; ps[t][1] = p1;
        g_assign[2 * (row0 + t)] = p0;
        g_assign[2 * (row0 + t) + 1] = p1;
    }
    __syncthreads();

    float s0 = 0.0f, s1v = 0.0f;
    #pragma unroll 4
    for (int n = 0; n < 128; n++) {
        float h = __bfloat162float(g_h2b[(size_t)(row0 + n) * 256 + t]);
        s0 += ps[n][0] * h;
        s1v += ps[n][1] * h;
    }
    atomicAdd(&g_gf[t], s0);
    atomicAdd(&g_gf[256 + t], s1v);
}

// ---------------- new_adj + finalize (last-block) + state restore ----------------
__global__ void k_newadj(const int* __restrict__ src, const int* __restrict__ dst,
                         float* __restrict__ out) {
    int gtid = blockIdx.x * blockDim.x + threadIdx.x;
    if (gtid < NN) g_deg[gtid] = 0;           // self-restore for graph replay
    float a0 = 0, a1 = 0, a2 = 0, a3 = 0;
    const float2* as2 = (const float2*)g_assign;
    for (int e = gtid; e < EE; e += gridDim.x * blockDim.x) {
        int s = src[e], d = dst[e];
        float2 sv = as2[s];
        float2 dv = as2[d];
        a0 += sv.x * dv.x; a1 += sv.x * dv.y; a2 += sv.y * dv.x; a3 += sv.y * dv.y;
    }
    #pragma unroll
    for (int w = 16; w; w >>= 1) {
        a0 += __shfl_down_sync(0xffffffff, a0, w);
        a1 += __shfl_down_sync(0xffffffff, a1, w);
        a2 += __shfl_down_sync(0xffffffff, a2, w);
        a3 += __shfl_down_sync(0xffffffff, a3, w);
    }
    __shared__ float sa[8][4];
    int lane = threadIdx.x & 31, wid = threadIdx.x >> 5;
    if (lane == 0) { sa[wid][0] = a0; sa[wid][1] = a1; sa[wid][2] = a2; sa[wid][3] = a3; }
    __syncthreads();
    if (threadIdx.x < 4) {
        float sum = 0;
        #pragma unroll
        for (int w = 0; w < 8; w++) sum += sa[w][threadIdx.x];
        atomicAdd(&g_newadj[threadIdx.x], sum);
        __threadfence();
    }
    __syncthreads();

    __shared__ int is_last;
    if (threadIdx.x == 0) {
        unsigned int ticket = atomicAdd(&g_done, 1);
        is_last = (ticket == gridDim.x - 1);
    }
    __syncthreads();
    if (is_last) {
        int t = threadIdx.x;
        float g0 = g_gf[t], g1 = g_gf[256 + t];
        g_gf[t] = 0.0f; g_gf[256 + t] = 0.0f;
        out[t]       = 0.5f * (g0 + g1);
        out[256 + t] = fminf(fmaxf(g0, -100.0f), 100.0f);
        out[512 + t] = fminf(fmaxf(g1, -100.0f), 100.0f);
        if (t == 0) {
            float b00 = g_newadj[0], b01 = g_newadj[1], b10 = g_newadj[2], b11 = g_newadj[3];
            g_newadj[0] = 0.0f; g_newadj[1] = 0.0f; g_newadj[2] = 0.0f; g_newadj[3] = 0.0f;
            g_done = 0;
            float den0 = fmaxf(fabsf(b00) + fabsf(b01), 1e-12f);
            float den1 = fmaxf(fabsf(b10) + fabsf(b11), 1e-12f);
            float nd0 = b00 / den0, nd1 = b11 / den1;
            out[768] = 0.5f * ((nd0 - 1.0f) * (nd0 - 1.0f) + (nd1 - 1.0f) * (nd1 - 1.0f));
        }
    }
}

extern "C" void kernel_launch(void* const* d_in, const int* in_sizes, int n_in,
                              void* d_out, int out_size) {
    const float* features = (const float*)d_in[0];
    const int*   edges    = (const int*)d_in[1];
    const float* W1    = (const float*)d_in[2];
    const float* b1    = (const float*)d_in[3];
    const float* W2    = (const float*)d_in[4];
    const float* b2    = (const float*)d_in[5];
    const float* fc1w  = (const float*)d_in[6];
    const float* fc1b  = (const float*)d_in[7];
    const float* fc2w  = (const float*)d_in[8];
    const float* fc2b  = (const float*)d_in[9];
    float* out = (float*)d_out;
    const int* src = edges;
    const int* dst = edges + EE;

    __nv_bfloat16 *pZb, *ph1b, *pXb;
    cudaGetSymbolAddress((void**)&pZb,  g_Zb);
    cudaGetSymbolAddress((void**)&ph1b, g_h1b);
    cudaGetSymbolAddress((void**)&pXb,  g_Xb);

    k_deg<<<EE / 1024, 1024>>>(dst, fc1w);          // + last-block scan/dinv
    k_scatter<<<EE / 256, 256>>>(src, dst, features);

    // layer 1: aggregate bf16 features (dinv premultiplied), tensor-core transform
    k_agg1<<<NN / 4, 256>>>();
    dim3 gg(2, NN / 128);
    k_gemm_tc<<<gg, 256>>>(pZb, W1, ph1b, b1, F_IN, 0);

    // layer 2: transform (bf16 out), aggregate (bf16 out)
    k_gemm_tc<<<gg, 256>>>(ph1b, W2, pXb, (const float*)0, H1, 1);
    k_agg2<<<NN / 4, 256>>>(b2);

    // fused MLP head
    k_fc1fc2<<<NN / 128, 256>>>(fc1b, fc2w, fc2b);

    // new_adj + finalize (fused, last-block)
    k_newadj<<<256, 256>>>(src, dst, out);
}

// round 15
// speedup vs baseline: 1.0368x; 1.0368x over previous
#include <cuda_runtime.h>
#include <cuda_bf16.h>
#include <cstdint>
#include <math.h>

#define NN     16384
#define EE     524288
#define F_IN   128
#define H1     256
#define H2     256
#define D1     64

// ---------------- scratch (device globals; no allocations) ----------------
// Self-restoring graph state: g_deg / g_gf / g_newadj / g_done reset each call.
__device__ __nv_bfloat16 g_Yb[NN * F_IN];  // dinv[r]*features, bf16
__device__ __nv_bfloat16 g_Zb[NN * F_IN];  // aggregated features, bf16
__device__ __nv_bfloat16 g_h1b[NN * H1];   // relu(Z@W1+b1), bf16
__device__ __nv_bfloat16 g_Xb[NN * H1];    // dinv*(h1@W2), bf16
__device__ __nv_bfloat16 g_h2b[NN * H2];   // layer-2 output, bf16
__device__ float g_dinv[NN];
__device__ int   g_deg[NN];
__device__ int   g_rowptr[NN + 1];
__device__ int   g_slot[EE];
__device__ int   g_col[EE];
__device__ float g_fc1wT[H2 * D1];
__device__ float g_assign[NN * 2];
__device__ float g_gf[2 * H2];
__device__ float g_newadj[4];
__device__ unsigned int g_done;

// ---------------- degree histogram (0-based slot) + fc1 transpose ----------------
__global__ void k_deg(const int* __restrict__ dst, const float* __restrict__ w) {
    int i = blockIdx.x * blockDim.x + threadIdx.x;
    g_slot[i] = atomicAdd(&g_deg[dst[i]], 1);
    if (i < D1 * H2) {
        int o = i >> 8, k = i & 255;
        g_fc1wT[k * D1 + o] = w[i];
    }
}

// ---------------- fused scan + dinv: 1 block, 1024 threads ----------------
__global__ __launch_bounds__(1024) void k_scan() {
    int t = threadIdx.x;
    int base = t * 16;
    int local[16];
    int s = 0;
    #pragma unroll
    for (int j = 0; j < 16; j++) {
        int dg = g_deg[base + j];
        g_dinv[base + j] = rsqrtf((float)(dg + 1));
        local[j] = s;
        s += dg;
    }
    int lane = t & 31, wid = t >> 5;
    int v = s;
    #pragma unroll
    for (int d = 1; d < 32; d <<= 1) {
        int u = __shfl_up_sync(0xffffffffu, v, d);
        if (lane >= d) v += u;
    }
    __shared__ int wsum[32];
    if (lane == 31) wsum[wid] = v;
    __syncthreads();
    if (wid == 0) {
        int w = wsum[lane];
        #pragma unroll
        for (int d = 1; d < 32; d <<= 1) {
            int u = __shfl_up_sync(0xffffffffu, w, d);
            if (lane >= d) w += u;
        }
        wsum[lane] = w;
    }
    __syncthreads();
    int off = (v - s) + (wid ? wsum[wid - 1] : 0);
    #pragma unroll
    for (int j = 0; j < 16; j++) g_rowptr[base + j] = off + local[j];
    if (t == 1023) g_rowptr[NN] = off + s;
}

// ---------------- atomic-free scatter + bf16(dinv*X) convert ----------------
__global__ void k_scatter(const int* __restrict__ src, const int* __restrict__ dst,
                          const float* __restrict__ X) {
    int i = blockIdx.x * blockDim.x + threadIdx.x;
    {
        int d = dst[i];
        g_col[g_rowptr[d] + g_slot[i]] = src[i];
    }
    {
        int node = i >> 5;
        float sc = g_dinv[node];
        float4 v = ((const float4*)X)[i];
        __nv_bfloat162 lo = __floats2bfloat162_rn(v.x * sc, v.y * sc);
        __nv_bfloat162 hi = __floats2bfloat162_rn(v.z * sc, v.w * sc);
        uint2 u; u.x = *(unsigned int*)&lo; u.y = *(unsigned int*)&hi;
        ((uint2*)g_Yb)[i] = u;
    }
}

// ---------------- bf16x2 SIMD add ----------------
__device__ __forceinline__ unsigned int h2add(unsigned int a, unsigned int b) {
    unsigned int r;
    asm("add.rn.bf16x2 %0, %1, %2;" : "=r"(r) : "r"(a), "r"(b));
    return r;
}

// ---------------- layer-1 aggregation: 2 warps/node, bf16-tree unroll-8 ----------------
__global__ __launch_bounds__(256) void k_agg1() {
    __shared__ float4 part[4][32];
    int t = threadIdx.x;
    int w = t >> 5, lane = t & 31;
    int n = w >> 1, half = w & 1;
    int d = blockIdx.x * 4 + n;
    const uint2* Y = (const uint2*)g_Yb;

    float4 acc = make_float4(0.f, 0.f, 0.f, 0.f);
    if (half == 0) {
        uint2 u = Y[d * 32 + lane];
        float2 a = __bfloat1622float2(*(__nv_bfloat162*)&u.x);
        float2 b = __bfloat1622float2(*(__nv_bfloat162*)&u.y);
        acc = make_float4(a.x, a.y, b.x, b.y);
    }
    int s0 = g_rowptr[d], s1 = g_rowptr[d + 1];
    int len = s1 - s0;
    int j    = s0 + ((len * half) >> 1);
    int jend = s0 + ((len * (half + 1)) >> 1);
    for (; j + 8 <= jend; j += 8) {
        int idx[8];
        uint2 uu[8];
        #pragma unroll
        for (int q = 0; q < 8; q++) idx[q] = g_col[j + q];
        #pragma unroll
        for (int q = 0; q < 8; q++) uu[q] = Y[idx[q] * 32 + lane];
        unsigned int s0x = h2add(uu[0].x, uu[1].x), s0y = h2add(uu[0].y, uu[1].y);
        unsigned int s1x = h2add(uu[2].x, uu[3].x), s1y = h2add(uu[2].y, uu[3].y);
        unsigned int s2x = h2add(uu[4].x, uu[5].x), s2y = h2add(uu[4].y, uu[5].y);
        unsigned int s3x = h2add(uu[6].x, uu[7].x), s3y = h2add(uu[6].y, uu[7].y);
        unsigned int t0x = h2add(s0x, s1x), t0y = h2add(s0y, s1y);
        unsigned int t1x = h2add(s2x, s3x), t1y = h2add(s2y, s3y);
        unsigned int rx = h2add(t0x, t1x), ry = h2add(t0y, t1y);
        float2 a = __bfloat1622float2(*(__nv_bfloat162*)&rx);
        float2 b = __bfloat1622float2(*(__nv_bfloat162*)&ry);
        acc.x += a.x; acc.y += a.y; acc.z += b.x; acc.w += b.y;
    }
    for (; j < jend; j++) {
        uint2 us = Y[g_col[j] * 32 + lane];
        float2 a = __bfloat1622float2(*(__nv_bfloat162*)&us.x);
        float2 b = __bfloat1622float2(*(__nv_bfloat162*)&us.y);
        acc.x += a.x; acc.y += a.y; acc.z += b.x; acc.w += b.y;
    }
    if (half == 1) part[n][lane] = acc;
    __syncthreads();
    if (half == 0) {
        float4 p = part[n][lane];
        float scd = g_dinv[d];
        __nv_bfloat162 lo = __floats2bfloat162_rn((acc.x + p.x) * scd, (acc.y + p.y) * scd);
        __nv_bfloat162 hi = __floats2bfloat162_rn((acc.z + p.z) * scd, (acc.w + p.w) * scd);
        uint2 o; o.x = *(unsigned int*)&lo; o.y = *(unsigned int*)&hi;
        ((uint2*)g_Zb)[d * 32 + lane] = o;
    }
}

// ---------------- tf32 helpers ----------------
__device__ __forceinline__ unsigned int f2tf32(float x) {
    unsigned int r;
    asm("cvt.rna.tf32.f32 %0, %1;" : "=r"(r) : "f"(x));
    return r;
}
__device__ __forceinline__ void mma_tf32(float* d, const unsigned int* a, const unsigned int* b) {
    asm volatile(
        "mma.sync.aligned.m16n8k8.row.col.f32.tf32.tf32.f32 "
        "{%0,%1,%2,%3},{%4,%5,%6,%7},{%8,%9},{%0,%1,%2,%3};\n"
        : "+f"(d[0]), "+f"(d[1]), "+f"(d[2]), "+f"(d[3])
        : "r"(a[0]), "r"(a[1]), "r"(a[2]), "r"(a[3]), "r"(b[0]), "r"(b[1]));
}

// ---------------- tf32 GEMM, 64x128 tile (occupancy-oriented), bf16 A, fp32 B; bf16 out ----------------
// mode 0: Cb = bf16(relu(AB + bias))   mode 1: Cb = bf16(dinv[row] * AB)
#define GBK 32
__global__ __launch_bounds__(256) void k_gemm_tc(const __nv_bfloat16* __restrict__ A,
                                                 const float* __restrict__ B,
                                                 __nv_bfloat16* __restrict__ Cb,
                                                 const float* __restrict__ bias,
                                                 int K, int mode) {
    __shared__ unsigned int As[GBK][72];    // [k][row 0..63]
    __shared__ unsigned int Bs[GBK][136];   // [k][col 0..127]
    int t = threadIdx.x;
    int row0 = blockIdx.y * 64, col0 = blockIdx.x * 128;
    int wid = t >> 5, lane = t & 31;
    int wr = wid >> 2, wc = wid & 3;        // warp tile: rows wr*32, cols wc*32
    int g = lane >> 2, tig = lane & 3;
    float acc[2][4][4] = {};

    int arr = t >> 2, akq = (t & 3) * 8;    // A: row 0..63, k-octet
    int bkr = t >> 5, bnq = (t & 31) * 4;   // B: 8 k-rows x 4 j-strides, col quad

    uint4 ra;                               // 8 bf16
    float4 rb[4];
    ra = *(const uint4*)&A[(size_t)(row0 + arr) * K + akq];
    #pragma unroll
    for (int j = 0; j < 4; j++)
        rb[j] = *(const float4*)&B[(size_t)(bkr + j * 8) * 256 + col0 + bnq];

    for (int k0 = 0; k0 < K; k0 += GBK) {
        {
            float2 p0 = __bfloat1622float2(*(__nv_bfloat162*)&ra.x);
            float2 p1 = __bfloat1622float2(*(__nv_bfloat162*)&ra.y);
            float2 p2 = __bfloat1622float2(*(__nv_bfloat162*)&ra.z);
            float2 p3 = __bfloat1622float2(*(__nv_bfloat162*)&ra.w);
            As[akq + 0][arr] = f2tf32(p0.x); As[akq + 1][arr] = f2tf32(p0.y);
            As[akq + 2][arr] = f2tf32(p1.x); As[akq + 3][arr] = f2tf32(p1.y);
            As[akq + 4][arr] = f2tf32(p2.x); As[akq + 5][arr] = f2tf32(p2.y);
            As[akq + 6][arr] = f2tf32(p3.x); As[akq + 7][arr] = f2tf32(p3.y);
        }
        #pragma unroll
        for (int j = 0; j < 4; j++) {
            int kr = bkr + j * 8;
            Bs[kr][bnq + 0] = f2tf32(rb[j].x); Bs[kr][bnq + 1] = f2tf32(rb[j].y);
            Bs[kr][bnq + 2] = f2tf32(rb[j].z); Bs[kr][bnq + 3] = f2tf32(rb[j].w);
        }
        __syncthreads();

        bool more = (k0 + GBK) < K;
        if (more) {
            ra = *(const uint4*)&A[(size_t)(row0 + arr) * K + k0 + GBK + akq];
            #pragma unroll
            for (int j = 0; j < 4; j++)
                rb[j] = *(const float4*)&B[(size_t)(k0 + GBK + bkr + j * 8) * 256 + col0 + bnq];
        }

        #pragma unroll
        for (int kk = 0; kk < GBK; kk += 8) {
            unsigned int af[2][4], bf[4][2];
            #pragma unroll
            for (int mi = 0; mi < 2; mi++) {
                int r = wr * 32 + mi * 16 + g;
                af[mi][0] = As[kk + tig][r];
                af[mi][1] = As[kk + tig][r + 8];
                af[mi][2] = As[kk + tig + 4][r];
                af[mi][3] = As[kk + tig + 4][r + 8];
            }
            #pragma unroll
            for (int ni = 0; ni < 4; ni++) {
                int c = wc * 32 + ni * 8 + g;
                bf[ni][0] = Bs[kk + tig][c];
                bf[ni][1] = Bs[kk + tig + 4][c];
            }
            #pragma unroll
            for (int mi = 0; mi < 2; mi++)
                #pragma unroll
                for (int ni = 0; ni < 4; ni++)
                    mma_tf32(acc[mi][ni], af[mi], bf[ni]);
        }
        __syncthreads();
    }

    #pragma unroll
    for (int mi = 0; mi < 2; mi++) {
        #pragma unroll
        for (int half = 0; half < 2; half++) {
            int r = row0 + wr * 32 + mi * 16 + g + half * 8;
            float sc = (mode == 1) ? g_dinv[r] : 1.0f;
            #pragma unroll
            for (int ni = 0; ni < 4; ni++) {
                int c = col0 + wc * 32 + ni * 8 + tig * 2;
                float v0 = acc[mi][ni][half * 2 + 0];
                float v1 = acc[mi][ni][half * 2 + 1];
                if (mode == 0) {
                    v0 = fmaxf(v0 + bias[c], 0.0f);
                    v1 = fmaxf(v1 + bias[c + 1], 0.0f);
                } else {
                    v0 *= sc; v1 *= sc;
                }
                __nv_bfloat162 bv = __floats2bfloat162_rn(v0, v1);
                *(__nv_bfloat162*)&Cb[(size_t)r * 256 + c] = bv;
            }
        }
    }
}

// ---------------- layer-2 aggregation: 2 groups (64 lanes)/node, bf16-tree unroll-8 ----------------
__global__ __launch_bounds__(256) void k_agg2(const float* __restrict__ bias) {
    __shared__ float4 part[2][64];
    int t = threadIdx.x;
    int grp = t >> 6;
    int lane = t & 63;
    int n = grp >> 1, half = grp & 1;
    int d = blockIdx.x * 2 + n;
    const uint2* Xb = (const uint2*)g_Xb;

    float4 acc = make_float4(0.f, 0.f, 0.f, 0.f);
    if (half == 0) {
        uint2 u = Xb[d * 64 + lane];
        float2 a = __bfloat1622float2(*(__nv_bfloat162*)&u.x);
        float2 b = __bfloat1622float2(*(__nv_bfloat162*)&u.y);
        acc = make_float4(a.x, a.y, b.x, b.y);
    }
    int s0 = g_rowptr[d], s1 = g_rowptr[d + 1];
    int len = s1 - s0;
    int j    = s0 + ((len * half) >> 1);
    int jend = s0 + ((len * (half + 1)) >> 1);
    for (; j + 8 <= jend; j += 8) {
        int idx[8];
        uint2 uu[8];
        #pragma unroll
        for (int q = 0; q < 8; q++) idx[q] = g_col[j + q];
        #pragma unroll
        for (int q = 0; q < 8; q++) uu[q] = Xb[idx[q] * 64 + lane];
        unsigned int s0x = h2add(uu[0].x, uu[1].x), s0y = h2add(uu[0].y, uu[1].y);
        unsigned int s1x = h2add(uu[2].x, uu[3].x), s1y = h2add(uu[2].y, uu[3].y);
        unsigned int s2x = h2add(uu[4].x, uu[5].x), s2y = h2add(uu[4].y, uu[5].y);
        unsigned int s3x = h2add(uu[6].x, uu[7].x), s3y = h2add(uu[6].y, uu[7].y);
        unsigned int t0x = h2add(s0x, s1x), t0y = h2add(s0y, s1y);
        unsigned int t1x = h2add(s2x, s3x), t1y = h2add(s2y, s3y);
        unsigned int rx = h2add(t0x, t1x), ry = h2add(t0y, t1y);
        float2 a = __bfloat1622float2(*(__nv_bfloat162*)&rx);
        float2 b = __bfloat1622float2(*(__nv_bfloat162*)&ry);
        acc.x += a.x; acc.y += a.y; acc.z += b.x; acc.w += b.y;
    }
    for (; j < jend; j++) {
        uint2 us = Xb[g_col[j] * 64 + lane];
        float2 a = __bfloat1622float2(*(__nv_bfloat162*)&us.x);
        float2 b = __bfloat1622float2(*(__nv_bfloat162*)&us.y);
        acc.x += a.x; acc.y += a.y; acc.z += b.x; acc.w += b.y;
    }
    if (half == 1) part[n][lane] = acc;
    __syncthreads();
    if (half == 0) {
        float4 p = part[n][lane];
        float sc = g_dinv[d];
        float4 bv = ((const float4*)bias)[lane];
        __nv_bfloat162 lo = __floats2bfloat162_rn((acc.x + p.x) * sc + bv.x,
                                                  (acc.y + p.y) * sc + bv.y);
        __nv_bfloat162 hi = __floats2bfloat162_rn((acc.z + p.z) * sc + bv.z,
                                                  (acc.w + p.w) * sc + bv.w);
        uint2 o; o.x = *(unsigned int*)&lo; o.y = *(unsigned int*)&hi;
        ((uint2*)g_h2b)[d * 64 + lane] = o;
    }
}

// ---------------- fused fc1 (tf32 MMA) + fc2 + softmax + assign + gf partials ----------------
__global__ __launch_bounds__(256) void k_fc1fc2(const float* __restrict__ fc1b,
                                                const float* __restrict__ fc2w,
                                                const float* __restrict__ fc2b) {
    __shared__ char buf[36864];
    unsigned int (*As)[136] = (unsigned int(*)[136])buf;
    unsigned int (*Bs)[72]  = (unsigned int(*)[72])(buf + 17408);
    float (*a1s)[65]  = (float(*)[65])buf;
    float (*ps)[2]    = (float(*)[2])(buf + 33280);
    float *w2s        = (float*)(buf + 34304);

    int t = threadIdx.x;
    int row0 = blockIdx.x * 128;
    int wid = t >> 5, lane = t & 31;
    int wr = wid >> 1, wc = wid & 1;
    int g = lane >> 2, tig = lane & 3;
    float acc[2][4][4] = {};

    int arr = t >> 3, akq = (t & 7) * 4;
    int bkr = t >> 3, bcq = (t & 7) * 8;

    const __nv_bfloat16* A = g_h2b;
    uint2 ra[4];
    float4 rb0, rb1;
    #pragma unroll
    for (int j = 0; j < 4; j++)
        ra[j] = *(const uint2*)&A[(size_t)(row0 + arr + j * 32) * 256 + akq];
    rb0 = *(const float4*)&g_fc1wT[(size_t)bkr * 64 + bcq];
    rb1 = *(const float4*)&g_fc1wT[(size_t)bkr * 64 + bcq + 4];

    for (int k0 = 0; k0 < 256; k0 += GBK) {
        #pragma unroll
        for (int j = 0; j < 4; j++) {
            int r = arr + j * 32;
            float2 lo = __bfloat1622float2(*(__nv_bfloat162*)&ra[j].x);
            float2 hi = __bfloat1622float2(*(__nv_bfloat162*)&ra[j].y);
            As[akq + 0][r] = f2tf32(lo.x); As[akq + 1][r] = f2tf32(lo.y);
            As[akq + 2][r] = f2tf32(hi.x); As[akq + 3][r] = f2tf32(hi.y);
        }
        Bs[bkr][bcq + 0] = f2tf32(rb0.x); Bs[bkr][bcq + 1] = f2tf32(rb0.y);
        Bs[bkr][bcq + 2] = f2tf32(rb0.z); Bs[bkr][bcq + 3] = f2tf32(rb0.w);
        Bs[bkr][bcq + 4] = f2tf32(rb1.x); Bs[bkr][bcq + 5] = f2tf32(rb1.y);
        Bs[bkr][bcq + 6] = f2tf32(rb1.z); Bs[bkr][bcq + 7] = f2tf32(rb1.w);
        __syncthreads();

        bool more = (k0 + GBK) < 256;
        if (more) {
            #pragma unroll
            for (int j = 0; j < 4; j++)
                ra[j] = *(const uint2*)&A[(size_t)(row0 + arr + j * 32) * 256 + k0 + GBK + akq];
            rb0 = *(const float4*)&g_fc1wT[(size_t)(k0 + GBK + bkr) * 64 + bcq];
            rb1 = *(const float4*)&g_fc1wT[(size_t)(k0 + GBK + bkr) * 64 + bcq + 4];
        }

        #pragma unroll
        for (int kk = 0; kk < GBK; kk += 8) {
            unsigned int af[2][4], bf[4][2];
            #pragma unroll
            for (int mi = 0; mi < 2; mi++) {
                int r = wr * 32 + mi * 16 + g;
                af[mi][0] = As[kk + tig][r];
                af[mi][1] = As[kk + tig][r + 8];
                af[mi][2] = As[kk + tig + 4][r];
                af[mi][3] = As[kk + tig + 4][r + 8];
            }
            #pragma unroll
            for (int ni = 0; ni < 4; ni++) {
                int c = wc * 32 + ni * 8 + g;
                bf[ni][0] = Bs[kk + tig][c];
                bf[ni][1] = Bs[kk + tig + 4][c];
            }
            #pragma unroll
            for (int mi = 0; mi < 2; mi++)
                #pragma unroll
                for (int ni = 0; ni < 4; ni++)
                    mma_tf32(acc[mi][ni], af[mi], bf[ni]);
        }
        __syncthreads();
    }
    #pragma unroll
    for (int mi = 0; mi < 2; mi++) {
        #pragma unroll
        for (int half = 0; half < 2; half++) {
            int rr = wr * 32 + mi * 16 + g + half * 8;
            #pragma unroll
            for (int ni = 0; ni < 4; ni++) {
                int c = wc * 32 + ni * 8 + tig * 2;
                a1s[rr][c]     = tanhf(acc[mi][ni][half * 2 + 0] + fc1b[c]);
                a1s[rr][c + 1] = tanhf(acc[mi][ni][half * 2 + 1] + fc1b[c + 1]);
            }
        }
    }
    if (t < 128) w2s[t] = fc2w[t];
    __syncthreads();

    {
        int n = t >> 1, c = t & 1;
        float l = fc2b[c];
        #pragma unroll
        for (int k = 0; k < 64; k++) l += w2s[c * 64 + k] * a1s[n][k];
        ps[n][c] = l;
    }
    __syncthreads();
    if (t < 128) {
        float l0 = ps[t][0], l1 = ps[t][1];
        float m = fmaxf(l0, l1);
        float e0 = expf(l0 - m), e1 = expf(l1 - m);
        float inv = 1.0f / (e0 + e1);
        float p0 = e0 * inv, p1 = e1 * inv;
        ps[t][0] = p0; ps[t][1] = p1;
        g_assign[2 * (row0 + t)] = p0;
        g_assign[2 * (row0 + t) + 1] = p1;
    }
    __syncthreads();

    float s0 = 0.0f, s1v = 0.0f;
    #pragma unroll 4
    for (int n = 0; n < 128; n++) {
        float h = __bfloat162float(g_h2b[(size_t)(row0 + n) * 256 + t]);
        s0 += ps[n][0] * h;
        s1v += ps[n][1] * h;
    }
    atomicAdd(&g_gf[t], s0);
    atomicAdd(&g_gf[256 + t], s1v);
}

// ---------------- new_adj + finalize (last-block) + state restore ----------------
__global__ void k_newadj(const int* __restrict__ src, const int* __restrict__ dst,
                         float* __restrict__ out) {
    int gtid = blockIdx.x * blockDim.x + threadIdx.x;
    if (gtid < NN) g_deg[gtid] = 0;
    float a0 = 0, a1 = 0, a2 = 0, a3 = 0;
    const float2* as2 = (const float2*)g_assign;
    for (int e = gtid; e < EE; e += gridDim.x * blockDim.x) {
        int s = src[e], d = dst[e];
        float2 sv = as2[s];
        float2 dv = as2[d];
        a0 += sv.x * dv.x; a1 += sv.x * dv.y; a2 += sv.y * dv.x; a3 += sv.y * dv.y;
    }
    #pragma unroll
    for (int w = 16; w; w >>= 1) {
        a0 += __shfl_down_sync(0xffffffff, a0, w);
        a1 += __shfl_down_sync(0xffffffff, a1, w);
        a2 += __shfl_down_sync(0xffffffff, a2, w);
        a3 += __shfl_down_sync(0xffffffff, a3, w);
    }
    __shared__ float sa[8][4];
    int lane = threadIdx.x & 31, wid = threadIdx.x >> 5;
    if (lane == 0) { sa[wid][0] = a0; sa[wid][1] = a1; sa[wid][2] = a2; sa[wid][3] = a3; }
    __syncthreads();
    if (threadIdx.x < 4) {
        float sum = 0;
        #pragma unroll
        for (int w = 0; w < 8; w++) sum += sa[w][threadIdx.x];
        atomicAdd(&g_newadj[threadIdx.x], sum);
        __threadfence();
    }
    __syncthreads();

    __shared__ int is_last;
    if (threadIdx.x == 0) {
        unsigned int ticket = atomicAdd(&g_done, 1);
        is_last = (ticket == gridDim.x - 1);
    }
    __syncthreads();
    if (is_last) {
        int t = threadIdx.x;
        float g0 = g_gf[t], g1 = g_gf[256 + t];
        g_gf[t] = 0.0f; g_gf[256 + t] = 0.0f;
        out[t]       = 0.5f * (g0 + g1);
        out[256 + t] = fminf(fmaxf(g0, -100.0f), 100.0f);
        out[512 + t] = fminf(fmaxf(g1, -100.0f), 100.0f);
        if (t == 0) {
            float b00 = g_newadj[0], b01 = g_newadj[1], b10 = g_newadj[2], b11 = g_newadj[3];
            g_newadj[0] = 0.0f; g_newadj[1] = 0.0f; g_newadj[2] = 0.0f; g_newadj[3] = 0.0f;
            g_done = 0;
            float den0 = fmaxf(fabsf(b00) + fabsf(b01), 1e-12f);
            float den1 = fmaxf(fabsf(b10) + fabsf(b11), 1e-12f);
            float nd0 = b00 / den0, nd1 = b11 / den1;
            out[768] = 0.5f * ((nd0 - 1.0f) * (nd0 - 1.0f) + (nd1 - 1.0f) * (nd1 - 1.0f));
        }
    }
}

extern "C" void kernel_launch(void* const* d_in, const int* in_sizes, int n_in,
                              void* d_out, int out_size) {
    const float* features = (const float*)d_in[0];
    const int*   edges    = (const int*)d_in[1];
    const float* W1    = (const float*)d_in[2];
    const float* b1    = (const float*)d_in[3];
    const float* W2    = (const float*)d_in[4];
    const float* b2    = (const float*)d_in[5];
    const float* fc1w  = (const float*)d_in[6];
    const float* fc1b  = (const float*)d_in[7];
    const float* fc2w  = (const float*)d_in[8];
    const float* fc2b  = (const float*)d_in[9];
    float* out = (float*)d_out;
    const int* src = edges;
    const int* dst = edges + EE;

    __nv_bfloat16 *pZb, *ph1b, *pXb;
    cudaGetSymbolAddress((void**)&pZb,  g_Zb);
    cudaGetSymbolAddress((void**)&ph1b, g_h1b);
    cudaGetSymbolAddress((void**)&pXb,  g_Xb);

    k_deg<<<EE / 256, 256>>>(dst, fc1w);
    k_scan<<<1, 1024>>>();
    k_scatter<<<EE / 256, 256>>>(src, dst, features);

    // layer 1: aggregate bf16 features (dinv premultiplied), tensor-core transform
    k_agg1<<<NN / 4, 256>>>();
    dim3 gg(2, NN / 64);
    k_gemm_tc<<<gg, 256>>>(pZb, W1, ph1b, b1, F_IN, 0);

    // layer 2: transform (bf16 out), aggregate (bf16 out)
    k_gemm_tc<<<gg, 256>>>(ph1b, W2, pXb, (const float*)0, H1, 1);
    k_agg2<<<NN / 2, 256>>>(b2);

    // fused MLP head
    k_fc1fc2<<<NN / 128, 256>>>(fc1b, fc2w, fc2b);

    // new_adj + finalize (fused, last-block)
    k_newadj<<<256, 256>>>(src, dst, out);
}

// round 16
// speedup vs baseline: 1.0745x; 1.0363x over previous
#include <cuda_runtime.h>
#include <cuda_bf16.h>
#include <cstdint>
#include <math.h>

#define NN     16384
#define EE     524288
#define F_IN   128
#define H1     256
#define H2     256
#define D1     64

// ---------------- scratch (device globals; no allocations) ----------------
// Self-restoring graph state: g_deg / g_gf / g_newadj / g_done reset each call.
__device__ __nv_bfloat16 g_Yb[NN * F_IN];  // dinv[r]*features, bf16
__device__ __nv_bfloat16 g_Zb[NN * F_IN];  // aggregated features, bf16
__device__ __nv_bfloat16 g_h1b[NN * H1];   // relu(Z@W1+b1), bf16
__device__ __nv_bfloat16 g_Xb[NN * H1];    // dinv*(h1@W2), bf16
__device__ __nv_bfloat16 g_h2b[NN * H2];   // layer-2 output, bf16
__device__ float g_dinv[NN];
__device__ int   g_deg[NN];
__device__ int   g_rowptr[NN + 1];
__device__ int   g_slot[EE];
__device__ int   g_col[EE];
__device__ float g_fc1wT[H2 * D1];
__device__ float g_assign[NN * 2];
__device__ float g_gf[2 * H2];
__device__ float g_newadj[4];
__device__ unsigned int g_done;

// ---------------- degree histogram (0-based slot) + fc1 transpose ----------------
__global__ void k_deg(const int* __restrict__ dst, const float* __restrict__ w) {
    int i = blockIdx.x * blockDim.x + threadIdx.x;
    g_slot[i] = atomicAdd(&g_deg[dst[i]], 1);
    if (i < D1 * H2) {
        int o = i >> 8, k = i & 255;
        g_fc1wT[k * D1 + o] = w[i];
    }
}

// ---------------- fused scan + dinv: 1 block, 1024 threads ----------------
__global__ __launch_bounds__(1024) void k_scan() {
    int t = threadIdx.x;
    int base = t * 16;
    int local[16];
    int s = 0;
    #pragma unroll
    for (int j = 0; j < 16; j++) {
        int dg = g_deg[base + j];
        g_dinv[base + j] = rsqrtf((float)(dg + 1));
        local[j] = s;
        s += dg;
    }
    int lane = t & 31, wid = t >> 5;
    int v = s;
    #pragma unroll
    for (int d = 1; d < 32; d <<= 1) {
        int u = __shfl_up_sync(0xffffffffu, v, d);
        if (lane >= d) v += u;
    }
    __shared__ int wsum[32];
    if (lane == 31) wsum[wid] = v;
    __syncthreads();
    if (wid == 0) {
        int w = wsum[lane];
        #pragma unroll
        for (int d = 1; d < 32; d <<= 1) {
            int u = __shfl_up_sync(0xffffffffu, w, d);
            if (lane >= d) w += u;
        }
        wsum[lane] = w;
    }
    __syncthreads();
    int off = (v - s) + (wid ? wsum[wid - 1] : 0);
    #pragma unroll
    for (int j = 0; j < 16; j++) g_rowptr[base + j] = off + local[j];
    if (t == 1023) g_rowptr[NN] = off + s;
}

// ---------------- atomic-free scatter + bf16(dinv*X) convert ----------------
__global__ void k_scatter(const int* __restrict__ src, const int* __restrict__ dst,
                          const float* __restrict__ X) {
    int i = blockIdx.x * blockDim.x + threadIdx.x;
    {
        int d = dst[i];
        g_col[g_rowptr[d] + g_slot[i]] = src[i];
    }
    {
        int node = i >> 5;
        float sc = g_dinv[node];
        float4 v = ((const float4*)X)[i];
        __nv_bfloat162 lo = __floats2bfloat162_rn(v.x * sc, v.y * sc);
        __nv_bfloat162 hi = __floats2bfloat162_rn(v.z * sc, v.w * sc);
        uint2 u; u.x = *(unsigned int*)&lo; u.y = *(unsigned int*)&hi;
        ((uint2*)g_Yb)[i] = u;
    }
}

// ---------------- bf16 SIMD helpers ----------------
__device__ __forceinline__ unsigned int h2add(unsigned int a, unsigned int b) {
    unsigned int r;
    asm("add.rn.bf16x2 %0, %1, %2;" : "=r"(r) : "r"(a), "r"(b));
    return r;
}
__device__ __forceinline__ uint4 h2add4(uint4 a, uint4 b) {
    uint4 r;
    r.x = h2add(a.x, b.x); r.y = h2add(a.y, b.y);
    r.z = h2add(a.z, b.z); r.w = h2add(a.w, b.w);
    return r;
}
__device__ __forceinline__ void acc8(float* acc, uint4 v) {
    float2 a = __bfloat1622float2(*(__nv_bfloat162*)&v.x);
    float2 b = __bfloat1622float2(*(__nv_bfloat162*)&v.y);
    float2 c = __bfloat1622float2(*(__nv_bfloat162*)&v.z);
    float2 e = __bfloat1622float2(*(__nv_bfloat162*)&v.w);
    acc[0] += a.x; acc[1] += a.y; acc[2] += b.x; acc[3] += b.y;
    acc[4] += c.x; acc[5] += c.y; acc[6] += e.x; acc[7] += e.y;
}
__device__ __forceinline__ uint4 pack8(const float* f) {
    __nv_bfloat162 p0 = __floats2bfloat162_rn(f[0], f[1]);
    __nv_bfloat162 p1 = __floats2bfloat162_rn(f[2], f[3]);
    __nv_bfloat162 p2 = __floats2bfloat162_rn(f[4], f[5]);
    __nv_bfloat162 p3 = __floats2bfloat162_rn(f[6], f[7]);
    uint4 o;
    o.x = *(unsigned int*)&p0; o.y = *(unsigned int*)&p1;
    o.z = *(unsigned int*)&p2; o.w = *(unsigned int*)&p3;
    return o;
}

// ---------------- layer-1 aggregation: 2 warps/node, bf16-tree unroll-8 (R13 proven) ----------------
__global__ __launch_bounds__(256) void k_agg1() {
    __shared__ float4 part[4][32];
    int t = threadIdx.x;
    int w = t >> 5, lane = t & 31;
    int n = w >> 1, half = w & 1;
    int d = blockIdx.x * 4 + n;
    const uint2* Y = (const uint2*)g_Yb;

    float4 acc = make_float4(0.f, 0.f, 0.f, 0.f);
    if (half == 0) {
        uint2 u = Y[d * 32 + lane];
        float2 a = __bfloat1622float2(*(__nv_bfloat162*)&u.x);
        float2 b = __bfloat1622float2(*(__nv_bfloat162*)&u.y);
        acc = make_float4(a.x, a.y, b.x, b.y);
    }
    int s0 = g_rowptr[d], s1 = g_rowptr[d + 1];
    int len = s1 - s0;
    int j    = s0 + ((len * half) >> 1);
    int jend = s0 + ((len * (half + 1)) >> 1);
    for (; j + 8 <= jend; j += 8) {
        int idx[8];
        uint2 uu[8];
        #pragma unroll
        for (int q = 0; q < 8; q++) idx[q] = g_col[j + q];
        #pragma unroll
        for (int q = 0; q < 8; q++) uu[q] = Y[idx[q] * 32 + lane];
        unsigned int s0x = h2add(uu[0].x, uu[1].x), s0y = h2add(uu[0].y, uu[1].y);
        unsigned int s1x = h2add(uu[2].x, uu[3].x), s1y = h2add(uu[2].y, uu[3].y);
        unsigned int s2x = h2add(uu[4].x, uu[5].x), s2y = h2add(uu[4].y, uu[5].y);
        unsigned int s3x = h2add(uu[6].x, uu[7].x), s3y = h2add(uu[6].y, uu[7].y);
        unsigned int t0x = h2add(s0x, s1x), t0y = h2add(s0y, s1y);
        unsigned int t1x = h2add(s2x, s3x), t1y = h2add(s2y, s3y);
        unsigned int rx = h2add(t0x, t1x), ry = h2add(t0y, t1y);
        float2 a = __bfloat1622float2(*(__nv_bfloat162*)&rx);
        float2 b = __bfloat1622float2(*(__nv_bfloat162*)&ry);
        acc.x += a.x; acc.y += a.y; acc.z += b.x; acc.w += b.y;
    }
    for (; j < jend; j++) {
        uint2 us = Y[g_col[j] * 32 + lane];
        float2 a = __bfloat1622float2(*(__nv_bfloat162*)&us.x);
        float2 b = __bfloat1622float2(*(__nv_bfloat162*)&us.y);
        acc.x += a.x; acc.y += a.y; acc.z += b.x; acc.w += b.y;
    }
    if (half == 1) part[n][lane] = acc;
    __syncthreads();
    if (half == 0) {
        float4 p = part[n][lane];
        float scd = g_dinv[d];
        __nv_bfloat162 lo = __floats2bfloat162_rn((acc.x + p.x) * scd, (acc.y + p.y) * scd);
        __nv_bfloat162 hi = __floats2bfloat162_rn((acc.z + p.z) * scd, (acc.w + p.w) * scd);
        uint2 o; o.x = *(unsigned int*)&lo; o.y = *(unsigned int*)&hi;
        ((uint2*)g_Zb)[d * 32 + lane] = o;
    }
}

// ---------------- tf32 helpers ----------------
__device__ __forceinline__ unsigned int f2tf32(float x) {
    unsigned int r;
    asm("cvt.rna.tf32.f32 %0, %1;" : "=r"(r) : "f"(x));
    return r;
}
__device__ __forceinline__ void mma_tf32(float* d, const unsigned int* a, const unsigned int* b) {
    asm volatile(
        "mma.sync.aligned.m16n8k8.row.col.f32.tf32.tf32.f32 "
        "{%0,%1,%2,%3},{%4,%5,%6,%7},{%8,%9},{%0,%1,%2,%3};\n"
        : "+f"(d[0]), "+f"(d[1]), "+f"(d[2]), "+f"(d[3])
        : "r"(a[0]), "r"(a[1]), "r"(a[2]), "r"(a[3]), "r"(b[0]), "r"(b[1]));
}

// ---------------- tf32 GEMM, 64x128 tile, bf16 A, fp32 B; bf16 out ----------------
#define GBK 32
__global__ __launch_bounds__(256) void k_gemm_tc(const __nv_bfloat16* __restrict__ A,
                                                 const float* __restrict__ B,
                                                 __nv_bfloat16* __restrict__ Cb,
                                                 const float* __restrict__ bias,
                                                 int K, int mode) {
    __shared__ unsigned int As[GBK][72];
    __shared__ unsigned int Bs[GBK][136];
    int t = threadIdx.x;
    int row0 = blockIdx.y * 64, col0 = blockIdx.x * 128;
    int wid = t >> 5, lane = t & 31;
    int wr = wid >> 2, wc = wid & 3;
    int g = lane >> 2, tig = lane & 3;
    float acc[2][4][4] = {};

    int arr = t >> 2, akq = (t & 3) * 8;
    int bkr = t >> 5, bnq = (t & 31) * 4;

    uint4 ra;
    float4 rb[4];
    ra = *(const uint4*)&A[(size_t)(row0 + arr) * K + akq];
    #pragma unroll
    for (int j = 0; j < 4; j++)
        rb[j] = *(const float4*)&B[(size_t)(bkr + j * 8) * 256 + col0 + bnq];

    for (int k0 = 0; k0 < K; k0 += GBK) {
        {
            float2 p0 = __bfloat1622float2(*(__nv_bfloat162*)&ra.x);
            float2 p1 = __bfloat1622float2(*(__nv_bfloat162*)&ra.y);
            float2 p2 = __bfloat1622float2(*(__nv_bfloat162*)&ra.z);
            float2 p3 = __bfloat1622float2(*(__nv_bfloat162*)&ra.w);
            As[akq + 0][arr] = f2tf32(p0.x); As[akq + 1][arr] = f2tf32(p0.y);
            As[akq + 2][arr] = f2tf32(p1.x); As[akq + 3][arr] = f2tf32(p1.y);
            As[akq + 4][arr] = f2tf32(p2.x); As[akq + 5][arr] = f2tf32(p2.y);
            As[akq + 6][arr] = f2tf32(p3.x); As[akq + 7][arr] = f2tf32(p3.y);
        }
        #pragma unroll
        for (int j = 0; j < 4; j++) {
            int kr = bkr + j * 8;
            Bs[kr][bnq + 0] = f2tf32(rb[j].x); Bs[kr][bnq + 1] = f2tf32(rb[j].y);
            Bs[kr][bnq + 2] = f2tf32(rb[j].z); Bs[kr][bnq + 3] = f2tf32(rb[j].w);
        }
        __syncthreads();

        bool more = (k0 + GBK) < K;
        if (more) {
            ra = *(const uint4*)&A[(size_t)(row0 + arr) * K + k0 + GBK + akq];
            #pragma unroll
            for (int j = 0; j < 4; j++)
                rb[j] = *(const float4*)&B[(size_t)(k0 + GBK + bkr + j * 8) * 256 + col0 + bnq];
        }

        #pragma unroll
        for (int kk = 0; kk < GBK; kk += 8) {
            unsigned int af[2][4], bf[4][2];
            #pragma unroll
            for (int mi = 0; mi < 2; mi++) {
                int r = wr * 32 + mi * 16 + g;
                af[mi][0] = As[kk + tig][r];
                af[mi][1] = As[kk + tig][r + 8];
                af[mi][2] = As[kk + tig + 4][r];
                af[mi][3] = As[kk + tig + 4][r + 8];
            }
            #pragma unroll
            for (int ni = 0; ni < 4; ni++) {
                int c = wc * 32 + ni * 8 + g;
                bf[ni][0] = Bs[kk + tig][c];
                bf[ni][1] = Bs[kk + tig + 4][c];
            }
            #pragma unroll
            for (int mi = 0; mi < 2; mi++)
                #pragma unroll
                for (int ni = 0; ni < 4; ni++)
                    mma_tf32(acc[mi][ni], af[mi], bf[ni]);
        }
        __syncthreads();
    }

    #pragma unroll
    for (int mi = 0; mi < 2; mi++) {
        #pragma unroll
        for (int half = 0; half < 2; half++) {
            int r = row0 + wr * 32 + mi * 16 + g + half * 8;
            float sc = (mode == 1) ? g_dinv[r] : 1.0f;
            #pragma unroll
            for (int ni = 0; ni < 4; ni++) {
                int c = col0 + wc * 32 + ni * 8 + tig * 2;
                float v0 = acc[mi][ni][half * 2 + 0];
                float v1 = acc[mi][ni][half * 2 + 1];
                if (mode == 0) {
                    v0 = fmaxf(v0 + bias[c], 0.0f);
                    v1 = fmaxf(v1 + bias[c + 1], 0.0f);
                } else {
                    v0 *= sc; v1 *= sc;
                }
                __nv_bfloat162 bv = __floats2bfloat162_rn(v0, v1);
                *(__nv_bfloat162*)&Cb[(size_t)r * 256 + c] = bv;
            }
        }
    }
}

// ---------------- layer-2 aggregation: 2 warps/node, full-warp uint4 gathers ----------------
__global__ __launch_bounds__(256) void k_agg2(const float* __restrict__ bias) {
    __shared__ float part[4][32][8];
    int t = threadIdx.x;
    int w = t >> 5, lane = t & 31;
    int n = w >> 1, half = w & 1;
    int d = blockIdx.x * 4 + n;
    const uint4* X4 = (const uint4*)g_Xb;   // 32 uint4 per 512B row

    float acc[8] = {};
    int s0 = g_rowptr[d], s1 = g_rowptr[d + 1];
    int len = s1 - s0;
    int j    = s0 + ((len * half) >> 1);
    int jend = s0 + ((len * (half + 1)) >> 1);
    for (; j + 8 <= jend; j += 8) {
        uint4 v[8];
        int idx[8];
        #pragma unroll
        for (int q = 0; q < 8; q++) idx[q] = g_col[j + q];
        #pragma unroll
        for (int q = 0; q < 8; q++) v[q] = X4[idx[q] * 32 + lane];
        uint4 a0 = h2add4(v[0], v[1]);
        uint4 a1 = h2add4(v[2], v[3]);
        uint4 a2 = h2add4(v[4], v[5]);
        uint4 a3 = h2add4(v[6], v[7]);
        uint4 b0 = h2add4(a0, a1);
        uint4 b1 = h2add4(a2, a3);
        acc8(acc, h2add4(b0, b1));
    }
    for (; j < jend; j++)
        acc8(acc, X4[g_col[j] * 32 + lane]);

    if (half == 1) {
        #pragma unroll
        for (int f = 0; f < 8; f++) part[n][lane][f] = acc[f];
    }
    __syncthreads();
    if (half == 0) {
        float sf[8];
        {   uint4 sv = X4[d * 32 + lane];   // self term
            float2 a = __bfloat1622float2(*(__nv_bfloat162*)&sv.x);
            float2 b = __bfloat1622float2(*(__nv_bfloat162*)&sv.y);
            float2 c = __bfloat1622float2(*(__nv_bfloat162*)&sv.z);
            float2 e = __bfloat1622float2(*(__nv_bfloat162*)&sv.w);
            sf[0] = a.x; sf[1] = a.y; sf[2] = b.x; sf[3] = b.y;
            sf[4] = c.x; sf[5] = c.y; sf[6] = e.x; sf[7] = e.y;
        }
        float sc = g_dinv[d];
        float4 bv0 = ((const float4*)bias)[lane * 2];
        float4 bv1 = ((const float4*)bias)[lane * 2 + 1];
        float bb[8] = {bv0.x, bv0.y, bv0.z, bv0.w, bv1.x, bv1.y, bv1.z, bv1.w};
        float o[8];
        #pragma unroll
        for (int f = 0; f < 8; f++)
            o[f] = (acc[f] + part[n][lane][f] + sf[f]) * sc + bb[f];
        ((uint4*)g_h2b)[d * 32 + lane] = pack8(o);
    }
}

// ---------------- fused fc1 (tf32 MMA) + fc2 + softmax + assign + gf partials ----------------
__global__ __launch_bounds__(256) void k_fc1fc2(const float* __restrict__ fc1b,
                                                const float* __restrict__ fc2w,
                                                const float* __restrict__ fc2b) {
    __shared__ char buf[36864];
    unsigned int (*As)[136] = (unsigned int(*)[136])buf;
    unsigned int (*Bs)[72]  = (unsigned int(*)[72])(buf + 17408);
    float (*a1s)[65]  = (float(*)[65])buf;                   // aliases As/Bs (dead after logits)
    float *gf0        = (float*)buf;                          // [8][256], aliases a1s (dead after softmax)
    float *gf1        = (float*)(buf + 8192);                 // [8][256]
    float (*ps)[2]    = (float(*)[2])(buf + 33280);
    float *w2s        = (float*)(buf + 34304);

    int t = threadIdx.x;
    int row0 = blockIdx.x * 128;
    int wid = t >> 5, lane = t & 31;
    int wr = wid >> 1, wc = wid & 1;
    int g = lane >> 2, tig = lane & 3;
    float acc[2][4][4] = {};

    int arr = t >> 3, akq = (t & 7) * 4;
    int bkr = t >> 3, bcq = (t & 7) * 8;

    const __nv_bfloat16* A = g_h2b;
    uint2 ra[4];
    float4 rb0, rb1;
    #pragma unroll
    for (int j = 0; j < 4; j++)
        ra[j] = *(const uint2*)&A[(size_t)(row0 + arr + j * 32) * 256 + akq];
    rb0 = *(const float4*)&g_fc1wT[(size_t)bkr * 64 + bcq];
    rb1 = *(const float4*)&g_fc1wT[(size_t)bkr * 64 + bcq + 4];

    for (int k0 = 0; k0 < 256; k0 += GBK) {
        #pragma unroll
        for (int j = 0; j < 4; j++) {
            int r = arr + j * 32;
            float2 lo = __bfloat1622float2(*(__nv_bfloat162*)&ra[j].x);
            float2 hi = __bfloat1622float2(*(__nv_bfloat162*)&ra[j].y);
            As[akq + 0][r] = f2tf32(lo.x); As[akq + 1][r] = f2tf32(lo.y);
            As[akq + 2][r] = f2tf32(hi.x); As[akq + 3][r] = f2tf32(hi.y);
        }
        Bs[bkr][bcq + 0] = f2tf32(rb0.x); Bs[bkr][bcq + 1] = f2tf32(rb0.y);
        Bs[bkr][bcq + 2] = f2tf32(rb0.z); Bs[bkr][bcq + 3] = f2tf32(rb0.w);
        Bs[bkr][bcq + 4] = f2tf32(rb1.x); Bs[bkr][bcq + 5] = f2tf32(rb1.y);
        Bs[bkr][bcq + 6] = f2tf32(rb1.z); Bs[bkr][bcq + 7] = f2tf32(rb1.w);
        __syncthreads();

        bool more = (k0 + GBK) < 256;
        if (more) {
            #pragma unroll
            for (int j = 0; j < 4; j++)
                ra[j] = *(const uint2*)&A[(size_t)(row0 + arr + j * 32) * 256 + k0 + GBK + akq];
            rb0 = *(const float4*)&g_fc1wT[(size_t)(k0 + GBK + bkr) * 64 + bcq];
            rb1 = *(const float4*)&g_fc1wT[(size_t)(k0 + GBK + bkr) * 64 + bcq + 4];
        }

        #pragma unroll
        for (int kk = 0; kk < GBK; kk += 8) {
            unsigned int af[2][4], bf[4][2];
            #pragma unroll
            for (int mi = 0; mi < 2; mi++) {
                int r = wr * 32 + mi * 16 + g;
                af[mi][0] = As[kk + tig][r];
                af[mi][1] = As[kk + tig][r + 8];
                af[mi][2] = As[kk + tig + 4][r];
                af[mi][3] = As[kk + tig + 4][r + 8];
            }
            #pragma unroll
            for (int ni = 0; ni < 4; ni++) {
                int c = wc * 32 + ni * 8 + g;
                bf[ni][0] = Bs[kk + tig][c];
                bf[ni][1] = Bs[kk + tig + 4][c];
            }
            #pragma unroll
            for (int mi = 0; mi < 2; mi++)
                #pragma unroll
                for (int ni = 0; ni < 4; ni++)
                    mma_tf32(acc[mi][ni], af[mi], bf[ni]);
        }
        __syncthreads();
    }
    #pragma unroll
    for (int mi = 0; mi < 2; mi++) {
        #pragma unroll
        for (int half = 0; half < 2; half++) {
            int rr = wr * 32 + mi * 16 + g + half * 8;
            #pragma unroll
            for (int ni = 0; ni < 4; ni++) {
                int c = wc * 32 + ni * 8 + tig * 2;
                a1s[rr][c]     = tanhf(acc[mi][ni][half * 2 + 0] + fc1b[c]);
                a1s[rr][c + 1] = tanhf(acc[mi][ni][half * 2 + 1] + fc1b[c + 1]);
            }
        }
    }
    if (t < 128) w2s[t] = fc2w[t];
    __syncthreads();

    {
        int n = t >> 1, c = t & 1;
        float l = fc2b[c];
        #pragma unroll
        for (int k = 0; k < 64; k++) l += w2s[c * 64 + k] * a1s[n][k];
        ps[n][c] = l;
    }
    __syncthreads();
    if (t < 128) {
        float l0 = ps[t][0], l1 = ps[t][1];
        float m = fmaxf(l0, l1);
        float e0 = expf(l0 - m), e1 = expf(l1 - m);
        float inv = 1.0f / (e0 + e1);
        float p0 = e0 * inv, p1 = e1 * inv;
        ps[t][0] = p0; ps[t][1] = p1;
        g_assign[2 * (row0 + t)] = p0;
        g_assign[2 * (row0 + t) + 1] = p1;
    }
    __syncthreads();   // a1s dead after this point; gf0/gf1 may reuse buf

    // gf partials, vectorized: thread t owns 8 features (lane*8..) of node i*8+warp
    {
        float s0[8] = {}, s1[8] = {};
        const uint4* H4 = (const uint4*)g_h2b;
        #pragma unroll 4
        for (int i = 0; i < 16; i++) {
            int n = i * 8 + wid;
            uint4 v = H4[(size_t)(row0 + n) * 32 + lane];
            float p0 = ps[n][0], p1 = ps[n][1];
            float2 a = __bfloat1622float2(*(__nv_bfloat162*)&v.x);
            float2 b = __bfloat1622float2(*(__nv_bfloat162*)&v.y);
            float2 c = __bfloat1622float2(*(__nv_bfloat162*)&v.z);
            float2 e = __bfloat1622float2(*(__nv_bfloat162*)&v.w);
            s0[0] += p0 * a.x; s0[1] += p0 * a.y; s0[2] += p0 * b.x; s0[3] += p0 * b.y;
            s0[4] += p0 * c.x; s0[5] += p0 * c.y; s0[6] += p0 * e.x; s0[7] += p0 * e.y;
            s1[0] += p1 * a.x; s1[1] += p1 * a.y; s1[2] += p1 * b.x; s1[3] += p1 * b.y;
            s1[4] += p1 * c.x; s1[5] += p1 * c.y; s1[6] += p1 * e.x; s1[7] += p1 * e.y;
        }
        #pragma unroll
        for (int f = 0; f < 8; f++) {
            gf0[wid * 256 + lane * 8 + f] = s0[f];
            gf1[wid * 256 + lane * 8 + f] = s1[f];
        }
    }
    __syncthreads();
    {
        float r0 = 0.0f, r1 = 0.0f;
        #pragma unroll
        for (int w = 0; w < 8; w++) {
            r0 += gf0[w * 256 + t];
            r1 += gf1[w * 256 + t];
        }
        atomicAdd(&g_gf[t], r0);
        atomicAdd(&g_gf[256 + t], r1);
    }
}

// ---------------- new_adj + finalize (last-block) + state restore ----------------
__global__ void k_newadj(const int* __restrict__ src, const int* __restrict__ dst,
                         float* __restrict__ out) {
    int gtid = blockIdx.x * blockDim.x + threadIdx.x;
    if (gtid < NN) g_deg[gtid] = 0;
    float a0 = 0, a1 = 0, a2 = 0, a3 = 0;
    const float2* as2 = (const float2*)g_assign;
    for (int e = gtid; e < EE; e += gridDim.x * blockDim.x) {
        int s = src[e], d = dst[e];
        float2 sv = as2[s];
        float2 dv = as2[d];
        a0 += sv.x * dv.x; a1 += sv.x * dv.y; a2 += sv.y * dv.x; a3 += sv.y * dv.y;
    }
    #pragma unroll
    for (int w = 16; w; w >>= 1) {
        a0 += __shfl_down_sync(0xffffffff, a0, w);
        a1 += __shfl_down_sync(0xffffffff, a1, w);
        a2 += __shfl_down_sync(0xffffffff, a2, w);
        a3 += __shfl_down_sync(0xffffffff, a3, w);
    }
    __shared__ float sa[8][4];
    int lane = threadIdx.x & 31, wid = threadIdx.x >> 5;
    if (lane == 0) { sa[wid][0] = a0; sa[wid][1] = a1; sa[wid][2] = a2; sa[wid][3] = a3; }
    __syncthreads();
    if (threadIdx.x < 4) {
        float sum = 0;
        #pragma unroll
        for (int w = 0; w < 8; w++) sum += sa[w][threadIdx.x];
        atomicAdd(&g_newadj[threadIdx.x], sum);
        __threadfence();
    }
    __syncthreads();

    __shared__ int is_last;
    if (threadIdx.x == 0) {
        unsigned int ticket = atomicAdd(&g_done, 1);
        is_last = (ticket == gridDim.x - 1);
    }
    __syncthreads();
    if (is_last) {
        int t = threadIdx.x;
        float g0 = g_gf[t], g1 = g_gf[256 + t];
        g_gf[t] = 0.0f; g_gf[256 + t] = 0.0f;
        out[t]       = 0.5f * (g0 + g1);
        out[256 + t] = fminf(fmaxf(g0, -100.0f), 100.0f);
        out[512 + t] = fminf(fmaxf(g1, -100.0f), 100.0f);
        if (t == 0) {
            float b00 = g_newadj[0], b01 = g_newadj[1], b10 = g_newadj[2], b11 = g_newadj[3];
            g_newadj[0] = 0.0f; g_newadj[1] = 0.0f; g_newadj[2] = 0.0f; g_newadj[3] = 0.0f;
            g_done = 0;
            float den0 = fmaxf(fabsf(b00) + fabsf(b01), 1e-12f);
            float den1 = fmaxf(fabsf(b10) + fabsf(b11), 1e-12f);
            float nd0 = b00 / den0, nd1 = b11 / den1;
            out[768] = 0.5f * ((nd0 - 1.0f) * (nd0 - 1.0f) + (nd1 - 1.0f) * (nd1 - 1.0f));
        }
    }
}

extern "C" void kernel_launch(void* const* d_in, const int* in_sizes, int n_in,
                              void* d_out, int out_size) {
    const float* features = (const float*)d_in[0];
    const int*   edges    = (const int*)d_in[1];
    const float* W1    = (const float*)d_in[2];
    const float* b1    = (const float*)d_in[3];
    const float* W2    = (const float*)d_in[4];
    const float* b2    = (const float*)d_in[5];
    const float* fc1w  = (const float*)d_in[6];
    const float* fc1b  = (const float*)d_in[7];
    const float* fc2w  = (const float*)d_in[8];
    const float* fc2b  = (const float*)d_in[9];
    float* out = (float*)d_out;
    const int* src = edges;
    const int* dst = edges + EE;

    __nv_bfloat16 *pZb, *ph1b, *pXb;
    cudaGetSymbolAddress((void**)&pZb,  g_Zb);
    cudaGetSymbolAddress((void**)&ph1b, g_h1b);
    cudaGetSymbolAddress((void**)&pXb,  g_Xb);

    k_deg<<<EE / 256, 256>>>(dst, fc1w);
    k_scan<<<1, 1024>>>();
    k_scatter<<<EE / 256, 256>>>(src, dst, features);

    // layer 1: aggregate bf16 features (dinv premultiplied), tensor-core transform
    k_agg1<<<NN / 4, 256>>>();
    dim3 gg(2, NN / 64);
    k_gemm_tc<<<gg, 256>>>(pZb, W1, ph1b, b1, F_IN, 0);

    // layer 2: transform (bf16 out), aggregate (bf16 out)
    k_gemm_tc<<<gg, 256>>>(ph1b, W2, pXb, (const float*)0, H1, 1);
    k_agg2<<<NN / 4, 256>>>(b2);

    // fused MLP head
    k_fc1fc2<<<NN / 128, 256>>>(fc1b, fc2w, fc2b);

    // new_adj + finalize (fused, last-block)
    k_newadj<<<256, 256>>>(src, dst, out);
}